// round 1
// baseline (speedup 1.0000x reference)
#include <cuda_runtime.h>
#include <math.h>

#define D_MODEL 1024
#define N_HEADS 16
#define HD 64
#define BATCH 2
#define SEQ 2048
#define M_TOTAL (BATCH * SEQ)   // 4096
#define QKV_N (3 * D_MODEL)     // 3072

// Scratch (device globals: allocation-free per harness rules)
__device__ float g_qkv[(size_t)M_TOTAL * QKV_N];   // [B*T, 3C]
__device__ float g_y[(size_t)M_TOTAL * D_MODEL];   // [B*T, C]

// ---------------------------------------------------------------------------
// SGEMM: C[M,N] = A[M,K] @ B[K,N] + bias[N]
// BM=BN=128, BK=8, 256 threads, 8x8 register tile (split 4+4 to reduce
// smem bank conflicts: thread owns cols {tc*4..+3, 64+tc*4..+3}).
// M,N multiples of 128; K multiple of 8. No bounds checks needed here.
// ---------------------------------------------------------------------------
__global__ __launch_bounds__(256) void sgemm_bias_kernel(
    const float* __restrict__ A, const float* __restrict__ B,
    const float* __restrict__ bias, float* __restrict__ C,
    int M, int N, int K)
{
    __shared__ float As[8][128];  // transposed A tile: As[k][m]
    __shared__ float Bs[8][128];  // Bs[k][n]

    const int tid = threadIdx.x;
    const int br = blockIdx.y, bc = blockIdx.x;

    const float* Ab = A + (size_t)br * 128 * K;
    const float* Bb = B + (size_t)bc * 128;

    // global load mapping
    const int aRow = tid >> 1;            // 0..127
    const int aCol = (tid & 1) * 4;       // 0 or 4
    const int bRow = tid >> 5;            // 0..7
    const int bCol = (tid & 31) * 4;      // 0..124

    // compute mapping
    const int tr = tid >> 4;              // 0..15
    const int tc = tid & 15;              // 0..15

    float acc[8][8];
#pragma unroll
    for (int i = 0; i < 8; i++)
#pragma unroll
        for (int j = 0; j < 8; j++) acc[i][j] = 0.f;

    for (int k0 = 0; k0 < K; k0 += 8) {
        float4 av = *reinterpret_cast<const float4*>(Ab + (size_t)aRow * K + k0 + aCol);
        float4 bv = *reinterpret_cast<const float4*>(Bb + (size_t)(k0 + bRow) * N + bCol);
        __syncthreads();  // protect smem reuse from previous iteration
        As[aCol + 0][aRow] = av.x;
        As[aCol + 1][aRow] = av.y;
        As[aCol + 2][aRow] = av.z;
        As[aCol + 3][aRow] = av.w;
        *reinterpret_cast<float4*>(&Bs[bRow][bCol]) = bv;
        __syncthreads();

#pragma unroll
        for (int kk = 0; kk < 8; kk++) {
            float4 a0 = *reinterpret_cast<const float4*>(&As[kk][tr * 4]);
            float4 a1 = *reinterpret_cast<const float4*>(&As[kk][64 + tr * 4]);
            float4 b0 = *reinterpret_cast<const float4*>(&Bs[kk][tc * 4]);
            float4 b1 = *reinterpret_cast<const float4*>(&Bs[kk][64 + tc * 4]);
            float ra[8] = {a0.x, a0.y, a0.z, a0.w, a1.x, a1.y, a1.z, a1.w};
            float rb[8] = {b0.x, b0.y, b0.z, b0.w, b1.x, b1.y, b1.z, b1.w};
#pragma unroll
            for (int i = 0; i < 8; i++)
#pragma unroll
                for (int j = 0; j < 8; j++) acc[i][j] += ra[i] * rb[j];
        }
    }

    // epilogue with bias
#pragma unroll
    for (int ih = 0; ih < 2; ih++) {
#pragma unroll
        for (int i4 = 0; i4 < 4; i4++) {
            int row = br * 128 + ih * 64 + tr * 4 + i4;
            int i = ih * 4 + i4;
#pragma unroll
            for (int jh = 0; jh < 2; jh++) {
                int col = bc * 128 + jh * 64 + tc * 4;
                float4 bb = *reinterpret_cast<const float4*>(bias + col);
                float4 o;
                o.x = acc[i][jh * 4 + 0] + bb.x;
                o.y = acc[i][jh * 4 + 1] + bb.y;
                o.z = acc[i][jh * 4 + 2] + bb.z;
                o.w = acc[i][jh * 4 + 3] + bb.w;
                *reinterpret_cast<float4*>(C + (size_t)row * N + col) = o;
            }
        }
    }
}

// ---------------------------------------------------------------------------
// Flash attention (causal), fp32.
// grid: (T/64 q-tiles, B*H). 256 threads. Each thread: one q-row r=tid>>2,
// key lane qq=tid&3 handling 16 strided keys j = qq + 4*jj (bank-conflict-free
// Ks reads), and 16 contiguous output dims d = qq*16 + dd.
// smem: Qs[64][68], Ks[64][68] (aliased as P after softmax), Vs[64][68].
// ---------------------------------------------------------------------------
#define AT_STRIDE 68
#define ATTN_SMEM (3 * 64 * AT_STRIDE * 4)

__global__ __launch_bounds__(256) void attn_kernel(
    const float* __restrict__ qkv, float* __restrict__ y)
{
    extern __shared__ float sm[];
    float* Qs = sm;                       // [64][AT_STRIDE]
    float* Ks = sm + 64 * AT_STRIDE;      // [64][AT_STRIDE]; aliased as P
    float* Vs = sm + 2 * 64 * AT_STRIDE;  // [64][AT_STRIDE]

    const int tid = threadIdx.x;
    const int bh = blockIdx.y;
    const int b = bh / N_HEADS;
    const int h = bh % N_HEADS;
    const int qt = blockIdx.x;
    const int q0 = qt * 64;

    const int rs = QKV_N;  // row stride in qkv
    const float* base = qkv + (size_t)b * SEQ * rs + h * HD;
    const float* Qg = base;
    const float* Kg = base + D_MODEL;
    const float* Vg = base + 2 * D_MODEL;

    const int r  = tid >> 2;  // 0..63 (q row within tile)
    const int qq = tid & 3;   // 0..3

    // load Q tile (each thread: 16 floats = 4x float4)
    {
        const int lr = tid >> 2, seg = tid & 3;
        const float* src = Qg + (size_t)(q0 + lr) * rs + seg * 16;
        float* dst = Qs + lr * AT_STRIDE + seg * 16;
#pragma unroll
        for (int i = 0; i < 4; i++)
            *reinterpret_cast<float4*>(dst + 4 * i) =
                *reinterpret_cast<const float4*>(src + 4 * i);
    }

    float m = -INFINITY, l = 0.f;
    float o[16];
#pragma unroll
    for (int i = 0; i < 16; i++) o[i] = 0.f;

    const float scale = 0.125f;  // 1/sqrt(64)
    const int qg = q0 + r;       // global query index
    const int ktiles = qt + 1;

    for (int kt = 0; kt < ktiles; kt++) {
        const int k0 = kt * 64;
        __syncthreads();  // previous iteration done with Ks(P)/Vs
        {
            const int lr = tid >> 2, seg = tid & 3;
            const float* srcK = Kg + (size_t)(k0 + lr) * rs + seg * 16;
            const float* srcV = Vg + (size_t)(k0 + lr) * rs + seg * 16;
            float* dstK = Ks + lr * AT_STRIDE + seg * 16;
            float* dstV = Vs + lr * AT_STRIDE + seg * 16;
#pragma unroll
            for (int i = 0; i < 4; i++) {
                *reinterpret_cast<float4*>(dstK + 4 * i) =
                    *reinterpret_cast<const float4*>(srcK + 4 * i);
                *reinterpret_cast<float4*>(dstV + 4 * i) =
                    *reinterpret_cast<const float4*>(srcV + 4 * i);
            }
        }
        __syncthreads();

        // S = Q K^T (this thread: 16 strided keys)
        float s[16];
#pragma unroll
        for (int i = 0; i < 16; i++) s[i] = 0.f;
#pragma unroll 4
        for (int k = 0; k < HD; k += 4) {
            float4 qv = *reinterpret_cast<const float4*>(Qs + r * AT_STRIDE + k);
#pragma unroll
            for (int jj = 0; jj < 16; jj++) {
                const int j = qq + 4 * jj;
                float4 kv = *reinterpret_cast<const float4*>(Ks + j * AT_STRIDE + k);
                s[jj] += qv.x * kv.x + qv.y * kv.y + qv.z * kv.z + qv.w * kv.w;
            }
        }
        // scale + causal mask
#pragma unroll
        for (int jj = 0; jj < 16; jj++) {
            const int jgl = k0 + qq + 4 * jj;
            s[jj] = (jgl <= qg) ? s[jj] * scale : -INFINITY;
        }

        // online softmax (row stats across the 4-lane quad)
        float mt = s[0];
#pragma unroll
        for (int jj = 1; jj < 16; jj++) mt = fmaxf(mt, s[jj]);
        mt = fmaxf(mt, __shfl_xor_sync(0xffffffffu, mt, 1));
        mt = fmaxf(mt, __shfl_xor_sync(0xffffffffu, mt, 2));
        const float mnew = fmaxf(m, mt);
        const float corr = __expf(m - mnew);  // 0 on first tile (m=-inf)

        float p[16];
        float psum = 0.f;
#pragma unroll
        for (int jj = 0; jj < 16; jj++) {
            p[jj] = __expf(s[jj] - mnew);  // masked -> exp(-inf) = 0
            psum += p[jj];
        }
        psum += __shfl_xor_sync(0xffffffffu, psum, 1);
        psum += __shfl_xor_sync(0xffffffffu, psum, 2);
        l = l * corr + psum;
        m = mnew;
#pragma unroll
        for (int i = 0; i < 16; i++) o[i] *= corr;

        __syncthreads();  // everyone done reading Ks before P overwrite
#pragma unroll
        for (int jj = 0; jj < 16; jj++)
            Ks[r * AT_STRIDE + qq + 4 * jj] = p[jj];
        __syncthreads();  // P visible to all

        // O += P @ V (this thread: dims d = qq*16 + dd)
        const float* Prow = Ks + r * AT_STRIDE;
        const float* Vbase = Vs + qq * 16;
#pragma unroll 8
        for (int j = 0; j < 64; j++) {
            const float pv = Prow[j];
            const float* vr = Vbase + j * AT_STRIDE;
#pragma unroll
            for (int dd = 0; dd < 16; dd += 4) {
                float4 vv = *reinterpret_cast<const float4*>(vr + dd);
                o[dd + 0] += pv * vv.x;
                o[dd + 1] += pv * vv.y;
                o[dd + 2] += pv * vv.z;
                o[dd + 3] += pv * vv.w;
            }
        }
    }

    // write out y[b, q0+r, h*64 + qq*16 + dd]
    const float inv = 1.f / l;
    float* yout = y + ((size_t)b * SEQ + q0 + r) * D_MODEL + h * HD + qq * 16;
#pragma unroll
    for (int dd = 0; dd < 16; dd += 4) {
        float4 ov;
        ov.x = o[dd + 0] * inv;
        ov.y = o[dd + 1] * inv;
        ov.z = o[dd + 2] * inv;
        ov.w = o[dd + 3] * inv;
        *reinterpret_cast<float4*>(yout + dd) = ov;
    }
}

// ---------------------------------------------------------------------------
extern "C" void kernel_launch(void* const* d_in, const int* in_sizes, int n_in,
                              void* d_out, int out_size)
{
    const float* x      = (const float*)d_in[0];
    const float* W_attn = (const float*)d_in[1];
    const float* b_attn = (const float*)d_in[2];
    const float* W_proj = (const float*)d_in[3];
    const float* b_proj = (const float*)d_in[4];
    float* out = (float*)d_out;

    float* qkv; cudaGetSymbolAddress((void**)&qkv, g_qkv);
    float* y;   cudaGetSymbolAddress((void**)&y, g_y);

    cudaFuncSetAttribute(attn_kernel,
                         cudaFuncAttributeMaxDynamicSharedMemorySize, ATTN_SMEM);

    // 1) qkv = x @ W_attn + b_attn   [4096,1024]@[1024,3072]
    sgemm_bias_kernel<<<dim3(QKV_N / 128, M_TOTAL / 128), 256>>>(
        x, W_attn, b_attn, qkv, M_TOTAL, QKV_N, D_MODEL);

    // 2) flash attention -> y [4096,1024]
    attn_kernel<<<dim3(SEQ / 64, BATCH * N_HEADS), 256, ATTN_SMEM>>>(qkv, y);

    // 3) out = y @ W_proj + b_proj   [4096,1024]@[1024,1024]
    sgemm_bias_kernel<<<dim3(D_MODEL / 128, M_TOTAL / 128), 256>>>(
        y, W_proj, b_proj, out, M_TOTAL, D_MODEL, D_MODEL);
}

// round 2
// speedup vs baseline: 1.8885x; 1.8885x over previous
#include <cuda_runtime.h>
#include <math.h>

#define D_MODEL 1024
#define N_HEADS 16
#define HD 64
#define BATCH 2
#define SEQ 2048
#define M_TOTAL (BATCH * SEQ)   // 4096
#define QKV_N (3 * D_MODEL)     // 3072

// Scratch (device globals: allocation-free per harness rules)
__device__ float g_qkv[(size_t)M_TOTAL * QKV_N];   // [B*T, 3C]
__device__ float g_y[(size_t)M_TOTAL * D_MODEL];   // [B*T, C]

// ---------------------------------------------------------------------------
// SGEMM: C[M,N] = A[M,K] @ B[K,N] + bias[N]
// BM=BN=128, BK=16, 256 threads, 8x8 register tile.
// Software-pipelined: next chunk's global loads issued right after the
// barrier so GMEM latency overlaps the 16-step FMA block.
// ---------------------------------------------------------------------------
__global__ __launch_bounds__(256) void sgemm_bias_kernel(
    const float* __restrict__ A, const float* __restrict__ B,
    const float* __restrict__ bias, float* __restrict__ C,
    int M, int N, int K)
{
    __shared__ float As[16][128];  // transposed A tile: As[k][m]
    __shared__ float Bs[16][128];  // Bs[k][n]

    const int tid = threadIdx.x;
    const int br = blockIdx.y, bc = blockIdx.x;

    const float* Ab = A + (size_t)br * 128 * K;
    const float* Bb = B + (size_t)bc * 128;

    // global load mapping
    const int aRow = tid & 127;           // 0..127 (warp = 32 consecutive rows)
    const int aCol = (tid >> 7) * 8;      // 0 or 8
    const int bRow = tid >> 4;            // 0..15
    const int bCol = (tid & 15) * 8;      // 0..120

    // compute mapping
    const int tr = tid >> 4;              // 0..15
    const int tc = tid & 15;              // 0..15

    float acc[8][8];
#pragma unroll
    for (int i = 0; i < 8; i++)
#pragma unroll
        for (int j = 0; j < 8; j++) acc[i][j] = 0.f;

    // prologue: prefetch chunk 0
    float4 av0 = *reinterpret_cast<const float4*>(Ab + (size_t)aRow * K + aCol);
    float4 av1 = *reinterpret_cast<const float4*>(Ab + (size_t)aRow * K + aCol + 4);
    float4 bv0 = *reinterpret_cast<const float4*>(Bb + (size_t)bRow * N + bCol);
    float4 bv1 = *reinterpret_cast<const float4*>(Bb + (size_t)bRow * N + bCol + 4);

    const int nc = K >> 4;
    for (int c = 0; c < nc; c++) {
        // store current chunk (conflict-free: warp stores 32 consecutive words)
        As[aCol + 0][aRow] = av0.x;
        As[aCol + 1][aRow] = av0.y;
        As[aCol + 2][aRow] = av0.z;
        As[aCol + 3][aRow] = av0.w;
        As[aCol + 4][aRow] = av1.x;
        As[aCol + 5][aRow] = av1.y;
        As[aCol + 6][aRow] = av1.z;
        As[aCol + 7][aRow] = av1.w;
        *reinterpret_cast<float4*>(&Bs[bRow][bCol]) = bv0;
        *reinterpret_cast<float4*>(&Bs[bRow][bCol + 4]) = bv1;
        __syncthreads();

        // prefetch next chunk (overlaps with compute below)
        if (c + 1 < nc) {
            const int k0 = (c + 1) * 16;
            av0 = *reinterpret_cast<const float4*>(Ab + (size_t)aRow * K + k0 + aCol);
            av1 = *reinterpret_cast<const float4*>(Ab + (size_t)aRow * K + k0 + aCol + 4);
            bv0 = *reinterpret_cast<const float4*>(Bb + (size_t)(k0 + bRow) * N + bCol);
            bv1 = *reinterpret_cast<const float4*>(Bb + (size_t)(k0 + bRow) * N + bCol + 4);
        }

#pragma unroll
        for (int kk = 0; kk < 16; kk++) {
            float4 a0 = *reinterpret_cast<const float4*>(&As[kk][tr * 4]);
            float4 a1 = *reinterpret_cast<const float4*>(&As[kk][64 + tr * 4]);
            float4 b0 = *reinterpret_cast<const float4*>(&Bs[kk][tc * 4]);
            float4 b1 = *reinterpret_cast<const float4*>(&Bs[kk][64 + tc * 4]);
            float ra[8] = {a0.x, a0.y, a0.z, a0.w, a1.x, a1.y, a1.z, a1.w};
            float rb[8] = {b0.x, b0.y, b0.z, b0.w, b1.x, b1.y, b1.z, b1.w};
#pragma unroll
            for (int i = 0; i < 8; i++)
#pragma unroll
                for (int j = 0; j < 8; j++) acc[i][j] += ra[i] * rb[j];
        }
        __syncthreads();
    }

    // epilogue with bias
#pragma unroll
    for (int ih = 0; ih < 2; ih++) {
#pragma unroll
        for (int i4 = 0; i4 < 4; i4++) {
            int row = br * 128 + ih * 64 + tr * 4 + i4;
            int i = ih * 4 + i4;
#pragma unroll
            for (int jh = 0; jh < 2; jh++) {
                int col = bc * 128 + jh * 64 + tc * 4;
                float4 bb = *reinterpret_cast<const float4*>(bias + col);
                float4 o;
                o.x = acc[i][jh * 4 + 0] + bb.x;
                o.y = acc[i][jh * 4 + 1] + bb.y;
                o.z = acc[i][jh * 4 + 2] + bb.z;
                o.w = acc[i][jh * 4 + 3] + bb.w;
                *reinterpret_cast<float4*>(C + (size_t)row * N + col) = o;
            }
        }
    }
}

// ---------------------------------------------------------------------------
// Flash attention (causal), fp32, register-blocked.
// grid: (T/64 q-tiles, B*H). 256 threads.
// Thread (tr=tid>>4, tc=tid&15) owns a 4x4 S tile:
//   rows r0..r0+3 (r0 = 4*tr, contiguous),
//   cols {tc, tc+16, tc+32, tc+48} (strided -> conflict-free Ks LDS.128).
// Row-group = 16 threads sharing tr (contiguous half-warp) -> shfl reductions.
// P is written TRANSPOSED (Pt[j][r], aliasing Ks) so PV reads are
// broadcast (Pt) + conflict-free (Vs).
// ---------------------------------------------------------------------------
#define AT_STRIDE 68
#define ATTN_SMEM (3 * 64 * AT_STRIDE * 4)

__global__ __launch_bounds__(256) void attn_kernel(
    const float* __restrict__ qkv, float* __restrict__ y)
{
    extern __shared__ float sm[];
    float* Qs = sm;                       // [64][AT_STRIDE]
    float* Ks = sm + 64 * AT_STRIDE;      // [64][AT_STRIDE]; aliased as Pt
    float* Vs = sm + 2 * 64 * AT_STRIDE;  // [64][AT_STRIDE]

    const int tid = threadIdx.x;
    const int bh = blockIdx.y;
    const int b = bh / N_HEADS;
    const int h = bh % N_HEADS;
    const int qt = blockIdx.x;
    const int q0 = qt * 64;

    const int rs = QKV_N;
    const float* base = qkv + (size_t)b * SEQ * rs + h * HD;
    const float* Qg = base;
    const float* Kg = base + D_MODEL;
    const float* Vg = base + 2 * D_MODEL;

    const int tr = tid >> 4;   // 0..15
    const int tc = tid & 15;   // 0..15
    const int r0 = 4 * tr;

    // load Q tile
    {
        const int lr = tid >> 2, seg = tid & 3;
        const float* src = Qg + (size_t)(q0 + lr) * rs + seg * 16;
        float* dst = Qs + lr * AT_STRIDE + seg * 16;
#pragma unroll
        for (int i = 0; i < 4; i++)
            *reinterpret_cast<float4*>(dst + 4 * i) =
                *reinterpret_cast<const float4*>(src + 4 * i);
    }

    float m[4], l[4], o[4][4];
#pragma unroll
    for (int i = 0; i < 4; i++) {
        m[i] = -INFINITY; l[i] = 0.f;
#pragma unroll
        for (int d = 0; d < 4; d++) o[i][d] = 0.f;
    }

    const float scale = 0.125f;  // 1/sqrt(64)

    for (int kt = 0; kt <= qt; kt++) {
        const int k0 = kt * 64;
        __syncthreads();  // prev iteration done reading Ks(Pt)/Vs
        {
            const int lr = tid >> 2, seg = tid & 3;
            const float* srcK = Kg + (size_t)(k0 + lr) * rs + seg * 16;
            const float* srcV = Vg + (size_t)(k0 + lr) * rs + seg * 16;
            float* dstK = Ks + lr * AT_STRIDE + seg * 16;
            float* dstV = Vs + lr * AT_STRIDE + seg * 16;
#pragma unroll
            for (int i = 0; i < 4; i++) {
                *reinterpret_cast<float4*>(dstK + 4 * i) =
                    *reinterpret_cast<const float4*>(srcK + 4 * i);
                *reinterpret_cast<float4*>(dstV + 4 * i) =
                    *reinterpret_cast<const float4*>(srcV + 4 * i);
            }
        }
        __syncthreads();

        // S = Q K^T : 4x4 outer-product tile, hd in float4 steps
        float s[4][4];
#pragma unroll
        for (int i = 0; i < 4; i++)
#pragma unroll
            for (int j = 0; j < 4; j++) s[i][j] = 0.f;

#pragma unroll 4
        for (int kk = 0; kk < 16; kk++) {
            float4 qv[4], kv[4];
#pragma unroll
            for (int i = 0; i < 4; i++)
                qv[i] = *reinterpret_cast<const float4*>(Qs + (r0 + i) * AT_STRIDE + 4 * kk);
#pragma unroll
            for (int j = 0; j < 4; j++)
                kv[j] = *reinterpret_cast<const float4*>(Ks + (tc + 16 * j) * AT_STRIDE + 4 * kk);
#pragma unroll
            for (int i = 0; i < 4; i++)
#pragma unroll
                for (int j = 0; j < 4; j++)
                    s[i][j] += qv[i].x * kv[j].x + qv[i].y * kv[j].y +
                               qv[i].z * kv[j].z + qv[i].w * kv[j].w;
        }

        // scale + causal mask (mask only needed on diagonal tile)
        if (kt == qt) {
#pragma unroll
            for (int i = 0; i < 4; i++) {
                const int qg = q0 + r0 + i;
#pragma unroll
                for (int j = 0; j < 4; j++) {
                    const int kg = k0 + tc + 16 * j;
                    s[i][j] = (kg <= qg) ? s[i][j] * scale : -INFINITY;
                }
            }
        } else {
#pragma unroll
            for (int i = 0; i < 4; i++)
#pragma unroll
                for (int j = 0; j < 4; j++) s[i][j] *= scale;
        }

        // online softmax per row (reduce across 16-thread row-group)
        float p[4][4];
#pragma unroll
        for (int i = 0; i < 4; i++) {
            float mt = fmaxf(fmaxf(s[i][0], s[i][1]), fmaxf(s[i][2], s[i][3]));
            mt = fmaxf(mt, __shfl_xor_sync(0xffffffffu, mt, 1));
            mt = fmaxf(mt, __shfl_xor_sync(0xffffffffu, mt, 2));
            mt = fmaxf(mt, __shfl_xor_sync(0xffffffffu, mt, 4));
            mt = fmaxf(mt, __shfl_xor_sync(0xffffffffu, mt, 8));
            const float mn = fmaxf(m[i], mt);
            const float corr = __expf(m[i] - mn);  // 0 on first tile
            float ps = 0.f;
#pragma unroll
            for (int j = 0; j < 4; j++) {
                p[i][j] = __expf(s[i][j] - mn);  // exp(-inf) = 0 for masked
                ps += p[i][j];
            }
            ps += __shfl_xor_sync(0xffffffffu, ps, 1);
            ps += __shfl_xor_sync(0xffffffffu, ps, 2);
            ps += __shfl_xor_sync(0xffffffffu, ps, 4);
            ps += __shfl_xor_sync(0xffffffffu, ps, 8);
            l[i] = l[i] * corr + ps;
            m[i] = mn;
#pragma unroll
            for (int d = 0; d < 4; d++) o[i][d] *= corr;
        }

        __syncthreads();  // all threads done reading Ks for S
        // write P transposed into Ks region: Pt[j][r]
#pragma unroll
        for (int j = 0; j < 4; j++) {
            float4 pw = make_float4(p[0][j], p[1][j], p[2][j], p[3][j]);
            *reinterpret_cast<float4*>(Ks + (tc + 16 * j) * AT_STRIDE + r0) = pw;
        }
        __syncthreads();

        // O += P @ V : per j, Pt row broadcast + Vs conflict-free
        const int c0 = 4 * tc;
#pragma unroll 8
        for (int j = 0; j < 64; j++) {
            float4 pv = *reinterpret_cast<const float4*>(Ks + j * AT_STRIDE + r0);
            float4 vv = *reinterpret_cast<const float4*>(Vs + j * AT_STRIDE + c0);
            o[0][0] += pv.x * vv.x; o[0][1] += pv.x * vv.y;
            o[0][2] += pv.x * vv.z; o[0][3] += pv.x * vv.w;
            o[1][0] += pv.y * vv.x; o[1][1] += pv.y * vv.y;
            o[1][2] += pv.y * vv.z; o[1][3] += pv.y * vv.w;
            o[2][0] += pv.z * vv.x; o[2][1] += pv.z * vv.y;
            o[2][2] += pv.z * vv.z; o[2][3] += pv.z * vv.w;
            o[3][0] += pv.w * vv.x; o[3][1] += pv.w * vv.y;
            o[3][2] += pv.w * vv.z; o[3][3] += pv.w * vv.w;
        }
    }

    // epilogue: y[b, q0+r0+i, h*64 + 4*tc + d]
#pragma unroll
    for (int i = 0; i < 4; i++) {
        const float inv = 1.f / l[i];
        float4 ov = make_float4(o[i][0] * inv, o[i][1] * inv,
                                o[i][2] * inv, o[i][3] * inv);
        *reinterpret_cast<float4*>(
            y + ((size_t)b * SEQ + q0 + r0 + i) * D_MODEL + h * HD + 4 * tc) = ov;
    }
}

// ---------------------------------------------------------------------------
extern "C" void kernel_launch(void* const* d_in, const int* in_sizes, int n_in,
                              void* d_out, int out_size)
{
    const float* x      = (const float*)d_in[0];
    const float* W_attn = (const float*)d_in[1];
    const float* b_attn = (const float*)d_in[2];
    const float* W_proj = (const float*)d_in[3];
    const float* b_proj = (const float*)d_in[4];
    float* out = (float*)d_out;

    float* qkv; cudaGetSymbolAddress((void**)&qkv, g_qkv);
    float* y;   cudaGetSymbolAddress((void**)&y, g_y);

    cudaFuncSetAttribute(attn_kernel,
                         cudaFuncAttributeMaxDynamicSharedMemorySize, ATTN_SMEM);

    // 1) qkv = x @ W_attn + b_attn   [4096,1024]@[1024,3072]
    sgemm_bias_kernel<<<dim3(QKV_N / 128, M_TOTAL / 128), 256>>>(
        x, W_attn, b_attn, qkv, M_TOTAL, QKV_N, D_MODEL);

    // 2) flash attention -> y [4096,1024]
    attn_kernel<<<dim3(SEQ / 64, BATCH * N_HEADS), 256, ATTN_SMEM>>>(qkv, y);

    // 3) out = y @ W_proj + b_proj   [4096,1024]@[1024,1024]
    sgemm_bias_kernel<<<dim3(D_MODEL / 128, M_TOTAL / 128), 256>>>(
        y, W_proj, b_proj, out, M_TOTAL, D_MODEL, D_MODEL);
}

// round 5
// speedup vs baseline: 2.5318x; 1.3406x over previous
#include <cuda_runtime.h>
#include <cuda_bf16.h>
#include <math.h>
#include <stdint.h>

#define D_MODEL 1024
#define N_HEADS 16
#define HD 64
#define BATCH 2
#define SEQ 2048
#define M_TOTAL (BATCH * SEQ)   // 4096
#define QKV_N (3 * D_MODEL)     // 3072
#define KDIM 1024

// ---------------- scratch (device globals; allocation-free) ----------------
__device__ float g_qkv[(size_t)M_TOTAL * QKV_N];
__device__ float g_y[(size_t)M_TOTAL * D_MODEL];

__device__ __align__(256) __nv_bfloat16 g_x_hi[(size_t)M_TOTAL * KDIM];
__device__ __align__(256) __nv_bfloat16 g_x_lo[(size_t)M_TOTAL * KDIM];
__device__ __align__(256) __nv_bfloat16 g_y_hi[(size_t)M_TOTAL * KDIM];
__device__ __align__(256) __nv_bfloat16 g_y_lo[(size_t)M_TOTAL * KDIM];
__device__ __align__(256) __nv_bfloat16 g_wat_hi[(size_t)QKV_N * KDIM];   // W_attn^T [3072,1024]
__device__ __align__(256) __nv_bfloat16 g_wat_lo[(size_t)QKV_N * KDIM];
__device__ __align__(256) __nv_bfloat16 g_wpt_hi[(size_t)D_MODEL * KDIM]; // W_proj^T [1024,1024]
__device__ __align__(256) __nv_bfloat16 g_wpt_lo[(size_t)D_MODEL * KDIM];

// ---------------- helpers ----------------
__device__ __forceinline__ uint32_t smem_u32(const void* p) {
    uint32_t a;
    asm("{ .reg .u64 t; cvta.to.shared.u64 t, %1; cvt.u32.u64 %0, t; }"
        : "=r"(a) : "l"(p));
    return a;
}

__device__ __forceinline__ void cp16(uint32_t dst, const void* src) {
    asm volatile("cp.async.cg.shared.global [%0], [%1], 16;" :: "r"(dst), "l"(src));
}
#define CP_COMMIT() asm volatile("cp.async.commit_group;" ::: "memory")
#define CP_WAIT(n)  asm volatile("cp.async.wait_group %0;" :: "n"(n) : "memory")

__device__ __forceinline__ void ldsm_x4(uint32_t* r, uint32_t addr) {
    asm volatile("ldmatrix.sync.aligned.m8n8.x4.shared.b16 {%0,%1,%2,%3}, [%4];"
        : "=r"(r[0]), "=r"(r[1]), "=r"(r[2]), "=r"(r[3]) : "r"(addr));
}

__device__ __forceinline__ void mma_bf16(float* d, const uint32_t* a,
                                         uint32_t b0, uint32_t b1) {
    asm volatile(
        "mma.sync.aligned.m16n8k16.row.col.f32.bf16.bf16.f32 "
        "{%0,%1,%2,%3}, {%4,%5,%6,%7}, {%8,%9}, {%0,%1,%2,%3};"
        : "+f"(d[0]), "+f"(d[1]), "+f"(d[2]), "+f"(d[3])
        : "r"(a[0]), "r"(a[1]), "r"(a[2]), "r"(a[3]), "r"(b0), "r"(b1));
}

// ---------------- conversion kernels ----------------
__device__ __forceinline__ void split1(float v, __nv_bfloat16& h, __nv_bfloat16& l) {
    h = __float2bfloat16(v);
    l = __float2bfloat16(v - __bfloat162float(h));
}

__global__ void split_kernel(const float* __restrict__ in,
                             __nv_bfloat16* __restrict__ hi,
                             __nv_bfloat16* __restrict__ lo, int n)
{
    int idx = (blockIdx.x * blockDim.x + threadIdx.x) * 4;
    if (idx >= n) return;
    float4 v = *reinterpret_cast<const float4*>(in + idx);
    __nv_bfloat16 h0, h1, h2, h3, l0, l1, l2, l3;
    split1(v.x, h0, l0); split1(v.y, h1, l1);
    split1(v.z, h2, l2); split1(v.w, h3, l3);
    *reinterpret_cast<__nv_bfloat162*>(hi + idx)     = __nv_bfloat162(h0, h1);
    *reinterpret_cast<__nv_bfloat162*>(hi + idx + 2) = __nv_bfloat162(h2, h3);
    *reinterpret_cast<__nv_bfloat162*>(lo + idx)     = __nv_bfloat162(l0, l1);
    *reinterpret_cast<__nv_bfloat162*>(lo + idx + 2) = __nv_bfloat162(l2, l3);
}

// W [K,N] -> Wt hi/lo [N,K]
__global__ void transpose_split_kernel(const float* __restrict__ W,
                                       __nv_bfloat16* __restrict__ th,
                                       __nv_bfloat16* __restrict__ tl,
                                       int K, int N)
{
    __shared__ float t[32][33];
    const int tx = threadIdx.x, ty = threadIdx.y;
    const int n0 = blockIdx.x * 32, k0 = blockIdx.y * 32;
#pragma unroll
    for (int j = ty; j < 32; j += 8)
        t[j][tx] = W[(size_t)(k0 + j) * N + n0 + tx];
    __syncthreads();
#pragma unroll
    for (int j = ty; j < 32; j += 8) {
        float v = t[tx][j];
        __nv_bfloat16 h, l;
        split1(v, h, l);
        size_t o = (size_t)(n0 + j) * K + k0 + tx;
        th[o] = h;
        tl[o] = l;
    }
}

// ---------------- mma.sync bf16 3-term GEMM ----------------
// C[M,N] = A[M,K] @ Bt[N,K]^T + bias   (Ah*Bh + Ah*Bl + Al*Bh, fp32 acc)
// CTA tile 128x128, BK=32, 8 warps of 64x32, cp.async double buffer.
#define TS 40                          // padded smem row stride (elems)
#define TILE_B (128 * TS * 2)          // 10240 B per tile
#define STAGE_B (4 * TILE_B)           // Ah, Al, Bh, Bl
#define GEMM_SMEM (2 * STAGE_B)        // 81920 B

__global__ __launch_bounds__(256) void gemm_mma_kernel(
    const __nv_bfloat16* __restrict__ Ah, const __nv_bfloat16* __restrict__ Al,
    const __nv_bfloat16* __restrict__ Bh, const __nv_bfloat16* __restrict__ Bl,
    const float* __restrict__ bias, float* __restrict__ C, int N)
{
    extern __shared__ char smem[];
    const uint32_t sbase = smem_u32(smem);
    const int tid = threadIdx.x;
    const int wid = tid >> 5, lane = tid & 31;
    const int m0 = blockIdx.y * 128, n0 = blockIdx.x * 128;
    const int wm = wid >> 2, wn = wid & 3;   // warp tile: rows wm*64, cols wn*32

    const __nv_bfloat16* aB[2] = {Ah + (size_t)m0 * KDIM, Al + (size_t)m0 * KDIM};
    const __nv_bfloat16* bB[2] = {Bh + (size_t)n0 * KDIM, Bl + (size_t)n0 * KDIM};

    float acc[4][4][4];
#pragma unroll
    for (int i = 0; i < 4; i++)
#pragma unroll
        for (int j = 0; j < 4; j++)
#pragma unroll
            for (int v = 0; v < 4; v++) acc[i][j][v] = 0.f;

    const int NC = KDIM / 32;  // 32 chunks

    auto issue = [&](int stage, int c) {
        const int k0 = c * 32;
        const uint32_t sb = sbase + stage * STAGE_B;
#pragma unroll
        for (int t = 0; t < 2; t++) {
#pragma unroll
            for (int i = 0; i < 2; i++) {
                const int cid = tid + 256 * i;
                const int r = cid >> 2, q = cid & 3;
                cp16(sb + t * TILE_B + (r * TS + q * 8) * 2,
                     aB[t] + (size_t)r * KDIM + k0 + q * 8);
                cp16(sb + (2 + t) * TILE_B + (r * TS + q * 8) * 2,
                     bB[t] + (size_t)r * KDIM + k0 + q * 8);
            }
        }
        CP_COMMIT();
    };

    issue(0, 0);

    for (int c = 0; c < NC; c++) {
        const int st = c & 1;
        if (c + 1 < NC) {
            issue((c + 1) & 1, c + 1);
            CP_WAIT(1);
        } else {
            CP_WAIT(0);
        }
        __syncthreads();

        const uint32_t sAh = sbase + st * STAGE_B;
        const uint32_t sAl = sAh + TILE_B;
        const uint32_t sBh = sAh + 2 * TILE_B;
        const uint32_t sBl = sAh + 3 * TILE_B;

        const int rowa = wm * 64 + (lane & 15);
        const int rowb = wn * 32 + (lane & 15);
        const int ko = (lane >> 4) * 8;

#pragma unroll
        for (int kt = 0; kt < 2; kt++) {
            const int k = kt * 16 + ko;
            uint32_t ah[4][4], al[4][4], bh[2][4], bl[2][4];
#pragma unroll
            for (int mt = 0; mt < 4; mt++) {
                ldsm_x4(ah[mt], sAh + ((rowa + mt * 16) * TS + k) * 2);
                ldsm_x4(al[mt], sAl + ((rowa + mt * 16) * TS + k) * 2);
            }
#pragma unroll
            for (int nt = 0; nt < 2; nt++) {
                ldsm_x4(bh[nt], sBh + ((rowb + nt * 16) * TS + k) * 2);
                ldsm_x4(bl[nt], sBl + ((rowb + nt * 16) * TS + k) * 2);
            }
            // B fragment pairing: for n-group h (0: n0-7, 1: n8-15) the mma
            // needs {k0-7, k8-15} = {r[h], r[h+2]} from ldmatrix.x4 on [n][k].
#pragma unroll
            for (int mt = 0; mt < 4; mt++)
#pragma unroll
                for (int nt = 0; nt < 2; nt++)
#pragma unroll
                    for (int h = 0; h < 2; h++) {
                        float* d = acc[mt][nt * 2 + h];
                        mma_bf16(d, ah[mt], bh[nt][h], bh[nt][h + 2]);
                        mma_bf16(d, ah[mt], bl[nt][h], bl[nt][h + 2]);
                        mma_bf16(d, al[mt], bh[nt][h], bh[nt][h + 2]);
                    }
        }
        __syncthreads();
    }

    // epilogue: fragment layout — g=lane>>2 row, tig=lane&3 col pair
    const int g = lane >> 2, tig = lane & 3;
#pragma unroll
    for (int mt = 0; mt < 4; mt++) {
#pragma unroll
        for (int n8 = 0; n8 < 4; n8++) {
            const int col = n0 + wn * 32 + n8 * 8 + tig * 2;
            const float2 bv = *reinterpret_cast<const float2*>(bias + col);
            const int row = m0 + wm * 64 + mt * 16 + g;
            float* d = acc[mt][n8];
            float2 o0 = make_float2(d[0] + bv.x, d[1] + bv.y);
            float2 o1 = make_float2(d[2] + bv.x, d[3] + bv.y);
            *reinterpret_cast<float2*>(C + (size_t)row * N + col) = o0;
            *reinterpret_cast<float2*>(C + (size_t)(row + 8) * N + col) = o1;
        }
    }
}

// ---------------------------------------------------------------------------
// Flash attention (causal), fp32, register-blocked.  (unchanged, validated)
// ---------------------------------------------------------------------------
#define AT_STRIDE 68
#define ATTN_SMEM (3 * 64 * AT_STRIDE * 4)

__global__ __launch_bounds__(256) void attn_kernel(
    const float* __restrict__ qkv, float* __restrict__ y)
{
    extern __shared__ float sm[];
    float* Qs = sm;
    float* Ks = sm + 64 * AT_STRIDE;
    float* Vs = sm + 2 * 64 * AT_STRIDE;

    const int tid = threadIdx.x;
    const int bh = blockIdx.y;
    const int b = bh / N_HEADS;
    const int h = bh % N_HEADS;
    const int qt = blockIdx.x;
    const int q0 = qt * 64;

    const int rs = QKV_N;
    const float* base = qkv + (size_t)b * SEQ * rs + h * HD;
    const float* Qg = base;
    const float* Kg = base + D_MODEL;
    const float* Vg = base + 2 * D_MODEL;

    const int tr = tid >> 4;
    const int tc = tid & 15;
    const int r0 = 4 * tr;

    {
        const int lr = tid >> 2, seg = tid & 3;
        const float* src = Qg + (size_t)(q0 + lr) * rs + seg * 16;
        float* dst = Qs + lr * AT_STRIDE + seg * 16;
#pragma unroll
        for (int i = 0; i < 4; i++)
            *reinterpret_cast<float4*>(dst + 4 * i) =
                *reinterpret_cast<const float4*>(src + 4 * i);
    }

    float m[4], l[4], o[4][4];
#pragma unroll
    for (int i = 0; i < 4; i++) {
        m[i] = -INFINITY; l[i] = 0.f;
#pragma unroll
        for (int d = 0; d < 4; d++) o[i][d] = 0.f;
    }

    const float scale = 0.125f;

    for (int kt = 0; kt <= qt; kt++) {
        const int k0 = kt * 64;
        __syncthreads();
        {
            const int lr = tid >> 2, seg = tid & 3;
            const float* srcK = Kg + (size_t)(k0 + lr) * rs + seg * 16;
            const float* srcV = Vg + (size_t)(k0 + lr) * rs + seg * 16;
            float* dstK = Ks + lr * AT_STRIDE + seg * 16;
            float* dstV = Vs + lr * AT_STRIDE + seg * 16;
#pragma unroll
            for (int i = 0; i < 4; i++) {
                *reinterpret_cast<float4*>(dstK + 4 * i) =
                    *reinterpret_cast<const float4*>(srcK + 4 * i);
                *reinterpret_cast<float4*>(dstV + 4 * i) =
                    *reinterpret_cast<const float4*>(srcV + 4 * i);
            }
        }
        __syncthreads();

        float s[4][4];
#pragma unroll
        for (int i = 0; i < 4; i++)
#pragma unroll
            for (int j = 0; j < 4; j++) s[i][j] = 0.f;

#pragma unroll 4
        for (int kk = 0; kk < 16; kk++) {
            float4 qv[4], kv[4];
#pragma unroll
            for (int i = 0; i < 4; i++)
                qv[i] = *reinterpret_cast<const float4*>(Qs + (r0 + i) * AT_STRIDE + 4 * kk);
#pragma unroll
            for (int j = 0; j < 4; j++)
                kv[j] = *reinterpret_cast<const float4*>(Ks + (tc + 16 * j) * AT_STRIDE + 4 * kk);
#pragma unroll
            for (int i = 0; i < 4; i++)
#pragma unroll
                for (int j = 0; j < 4; j++)
                    s[i][j] += qv[i].x * kv[j].x + qv[i].y * kv[j].y +
                               qv[i].z * kv[j].z + qv[i].w * kv[j].w;
        }

        if (kt == qt) {
#pragma unroll
            for (int i = 0; i < 4; i++) {
                const int qg = q0 + r0 + i;
#pragma unroll
                for (int j = 0; j < 4; j++) {
                    const int kg = k0 + tc + 16 * j;
                    s[i][j] = (kg <= qg) ? s[i][j] * scale : -INFINITY;
                }
            }
        } else {
#pragma unroll
            for (int i = 0; i < 4; i++)
#pragma unroll
                for (int j = 0; j < 4; j++) s[i][j] *= scale;
        }

        float p[4][4];
#pragma unroll
        for (int i = 0; i < 4; i++) {
            float mt = fmaxf(fmaxf(s[i][0], s[i][1]), fmaxf(s[i][2], s[i][3]));
            mt = fmaxf(mt, __shfl_xor_sync(0xffffffffu, mt, 1));
            mt = fmaxf(mt, __shfl_xor_sync(0xffffffffu, mt, 2));
            mt = fmaxf(mt, __shfl_xor_sync(0xffffffffu, mt, 4));
            mt = fmaxf(mt, __shfl_xor_sync(0xffffffffu, mt, 8));
            const float mn = fmaxf(m[i], mt);
            const float corr = __expf(m[i] - mn);
            float ps = 0.f;
#pragma unroll
            for (int j = 0; j < 4; j++) {
                p[i][j] = __expf(s[i][j] - mn);
                ps += p[i][j];
            }
            ps += __shfl_xor_sync(0xffffffffu, ps, 1);
            ps += __shfl_xor_sync(0xffffffffu, ps, 2);
            ps += __shfl_xor_sync(0xffffffffu, ps, 4);
            ps += __shfl_xor_sync(0xffffffffu, ps, 8);
            l[i] = l[i] * corr + ps;
            m[i] = mn;
#pragma unroll
            for (int d = 0; d < 4; d++) o[i][d] *= corr;
        }

        __syncthreads();
#pragma unroll
        for (int j = 0; j < 4; j++) {
            float4 pw = make_float4(p[0][j], p[1][j], p[2][j], p[3][j]);
            *reinterpret_cast<float4*>(Ks + (tc + 16 * j) * AT_STRIDE + r0) = pw;
        }
        __syncthreads();

        const int c0 = 4 * tc;
#pragma unroll 8
        for (int j = 0; j < 64; j++) {
            float4 pv = *reinterpret_cast<const float4*>(Ks + j * AT_STRIDE + r0);
            float4 vv = *reinterpret_cast<const float4*>(Vs + j * AT_STRIDE + c0);
            o[0][0] += pv.x * vv.x; o[0][1] += pv.x * vv.y;
            o[0][2] += pv.x * vv.z; o[0][3] += pv.x * vv.w;
            o[1][0] += pv.y * vv.x; o[1][1] += pv.y * vv.y;
            o[1][2] += pv.y * vv.z; o[1][3] += pv.y * vv.w;
            o[2][0] += pv.z * vv.x; o[2][1] += pv.z * vv.y;
            o[2][2] += pv.z * vv.z; o[2][3] += pv.z * vv.w;
            o[3][0] += pv.w * vv.x; o[3][1] += pv.w * vv.y;
            o[3][2] += pv.w * vv.z; o[3][3] += pv.w * vv.w;
        }
    }

#pragma unroll
    for (int i = 0; i < 4; i++) {
        const float inv = 1.f / l[i];
        float4 ov = make_float4(o[i][0] * inv, o[i][1] * inv,
                                o[i][2] * inv, o[i][3] * inv);
        *reinterpret_cast<float4*>(
            y + ((size_t)b * SEQ + q0 + r0 + i) * D_MODEL + h * HD + 4 * tc) = ov;
    }
}

// ---------------------------------------------------------------------------
extern "C" void kernel_launch(void* const* d_in, const int* in_sizes, int n_in,
                              void* d_out, int out_size)
{
    const float* x      = (const float*)d_in[0];
    const float* W_attn = (const float*)d_in[1];
    const float* b_attn = (const float*)d_in[2];
    const float* W_proj = (const float*)d_in[3];
    const float* b_proj = (const float*)d_in[4];
    float* out = (float*)d_out;

    float *qkv, *y;
    __nv_bfloat16 *xh, *xl, *yh, *yl, *wah, *wal, *wph, *wpl;
    cudaGetSymbolAddress((void**)&qkv, g_qkv);
    cudaGetSymbolAddress((void**)&y, g_y);
    cudaGetSymbolAddress((void**)&xh, g_x_hi);
    cudaGetSymbolAddress((void**)&xl, g_x_lo);
    cudaGetSymbolAddress((void**)&yh, g_y_hi);
    cudaGetSymbolAddress((void**)&yl, g_y_lo);
    cudaGetSymbolAddress((void**)&wah, g_wat_hi);
    cudaGetSymbolAddress((void**)&wal, g_wat_lo);
    cudaGetSymbolAddress((void**)&wph, g_wpt_hi);
    cudaGetSymbolAddress((void**)&wpl, g_wpt_lo);

    cudaFuncSetAttribute(attn_kernel,
                         cudaFuncAttributeMaxDynamicSharedMemorySize, ATTN_SMEM);
    cudaFuncSetAttribute(gemm_mma_kernel,
                         cudaFuncAttributeMaxDynamicSharedMemorySize, GEMM_SMEM);

    const int NX = M_TOTAL * KDIM;

    // prep: split x, transpose+split weights
    split_kernel<<<NX / (256 * 4), 256>>>(x, xh, xl, NX);
    transpose_split_kernel<<<dim3(QKV_N / 32, KDIM / 32), dim3(32, 8)>>>(
        W_attn, wah, wal, KDIM, QKV_N);
    transpose_split_kernel<<<dim3(D_MODEL / 32, KDIM / 32), dim3(32, 8)>>>(
        W_proj, wph, wpl, KDIM, D_MODEL);

    // 1) qkv = x @ W_attn + b_attn (tensor cores via mma.sync)
    gemm_mma_kernel<<<dim3(QKV_N / 128, M_TOTAL / 128), 256, GEMM_SMEM>>>(
        xh, xl, wah, wal, b_attn, qkv, QKV_N);

    // 2) flash attention -> y
    attn_kernel<<<dim3(SEQ / 64, BATCH * N_HEADS), 256, ATTN_SMEM>>>(qkv, y);

    // 3) out = y @ W_proj + b_proj
    split_kernel<<<NX / (256 * 4), 256>>>(y, yh, yl, NX);
    gemm_mma_kernel<<<dim3(D_MODEL / 128, M_TOTAL / 128), 256, GEMM_SMEM>>>(
        yh, yl, wph, wpl, b_proj, out, D_MODEL);
}